// round 17
// baseline (speedup 1.0000x reference)
#include <cuda_runtime.h>
#include <cuda_fp16.h>
#include <cstdint>

#define CC 256
#define NN 4096

// Scratch (device globals) — all attention-side tensors fp16
__device__ __half g_qf[128 * 32 * 1024];   // [bh][d][na], pre-scaled hd^-0.5*log2(e)
__device__ __half g_kf[128 * 32 * 1024];   // [bh][d][na]
__device__ __half g_vp[128 * 32 * 1024];   // [bh][d][na]
__device__ float g_tmp[4 * 256 * 4096];    // [b][c][n] attn out fp32
__device__ __half g_xf[4 * 256 * 4096];    // x fp16
__device__ __half g_tf[4 * 256 * 4096];    // (attn+pe) fp16
__device__ __half g_wqf[768 * 256];        // w_qkv fp16
__device__ __half g_wpf[256 * 256];        // w_proj fp16

// ---------------- helpers ----------------
__device__ __forceinline__ uint32_t smem_to_u32(const void* p) {
    uint32_t a;
    asm("{ .reg .u64 t; cvta.to.shared.u64 t, %1; cvt.u32.u64 %0, t; }" : "=r"(a) : "l"(p));
    return a;
}
__device__ __forceinline__ void cp16(uint32_t saddr, const void* g) {
    asm volatile("cp.async.cg.shared.global [%0], [%1], 16;" :: "r"(saddr), "l"(g) : "memory");
}
__device__ __forceinline__ void ldsm4(uint32_t r[4], uint32_t addr) {
    asm volatile("ldmatrix.sync.aligned.m8n8.x4.shared.b16 {%0,%1,%2,%3}, [%4];"
                 : "=r"(r[0]), "=r"(r[1]), "=r"(r[2]), "=r"(r[3]) : "r"(addr));
}
__device__ __forceinline__ void ldsm4t(uint32_t r[4], uint32_t addr) {
    asm volatile("ldmatrix.sync.aligned.m8n8.x4.trans.shared.b16 {%0,%1,%2,%3}, [%4];"
                 : "=r"(r[0]), "=r"(r[1]), "=r"(r[2]), "=r"(r[3]) : "r"(addr));
}
__device__ __forceinline__ void mma16816h(float c[4], const uint32_t a[4], const uint32_t b[2]) {
    asm volatile("mma.sync.aligned.m16n8k16.row.col.f32.f16.f16.f32 "
                 "{%0,%1,%2,%3}, {%4,%5,%6,%7}, {%8,%9}, {%0,%1,%2,%3};"
                 : "+f"(c[0]), "+f"(c[1]), "+f"(c[2]), "+f"(c[3])
                 : "r"(a[0]), "r"(a[1]), "r"(a[2]), "r"(a[3]), "r"(b[0]), "r"(b[1]));
}
__device__ __forceinline__ uint32_t h2pack(float a, float b) {
    __half2 h = __floats2half2_rn(a, b);
    return *(uint32_t*)&h;
}
__device__ __forceinline__ uint32_t ex2h2(uint32_t s) {
    uint32_t r;
    asm("ex2.approx.f16x2 %0, %1;" : "=r"(r) : "r"(s));
    return r;
}

// ---------------------------------------------------------------------------
// Kernel 0: convert x + both weights -> fp16 (single launch).
// ---------------------------------------------------------------------------
__global__ __launch_bounds__(256) void conv_all(const float* __restrict__ x,
                                                const float* __restrict__ wq,
                                                const float* __restrict__ wp) {
    int id = blockIdx.x * 256 + threadIdx.x;
    const float* src;
    __half* dst;
    size_t off;
    if (id < 49152)       { src = wq; dst = g_wqf; off = (size_t)id * 4; }
    else if (id < 65536)  { src = wp; dst = g_wpf; off = (size_t)(id - 49152) * 4; }
    else                  { src = x;  dst = g_xf;  off = (size_t)(id - 65536) * 4; }
    float4 v = *(const float4*)&src[off];
    *(uint2*)&dst[off] = make_uint2(h2pack(v.x, v.y), h2pack(v.z, v.w));
}

// ---------------------------------------------------------------------------
// GEMM core: single fp16, cp.async double buffer (unchanged).
// ---------------------------------------------------------------------------
#define GBUF 18944
#define GSMEM (2 * GBUF)

__device__ __forceinline__ void gemm_core(float c[2][8][4], uint8_t* shm,
                                          const __half* __restrict__ xf,
                                          const __half* __restrict__ wf) {
    const int t = threadIdx.x, lane = t & 31, wid = t >> 5;
    const int wm = wid >> 1, wn = wid & 1;
    const int nBase = blockIdx.x * 128, oBase = blockIdx.y * 128;
    const uint32_t sb = smem_to_u32(shm);
    const int grp = lane >> 3;

    auto stage = [&](int buf, int kc) {
        const int k0 = kc * 32;
        uint32_t base = sb + buf * GBUF;
#pragma unroll
        for (int e = 0; e < 2; e++) {
            int cid = e * 256 + t;
            int row = cid >> 2, col = cid & 3;
            cp16(base + row * 80 + col * 16, wf + (size_t)(oBase + row) * 256 + k0 + col * 8);
        }
#pragma unroll
        for (int e = 0; e < 2; e++) {
            int cid = e * 256 + t;
            int row = cid >> 4, col = cid & 15;
            cp16(base + 10240 + row * 272 + col * 16, xf + (size_t)(k0 + row) * 4096 + nBase + col * 8);
        }
        asm volatile("cp.async.commit_group;" ::: "memory");
    };

    stage(0, 0);
    for (int kc = 0; kc < 8; kc++) {
        if (kc < 7) {
            stage((kc + 1) & 1, kc + 1);
            asm volatile("cp.async.wait_group 1;" ::: "memory");
        } else {
            asm volatile("cp.async.wait_group 0;" ::: "memory");
        }
        __syncthreads();
        const uint32_t base = sb + (kc & 1) * GBUF;

        uint32_t ah[2][2][4];
#pragma unroll
        for (int kk = 0; kk < 2; kk++)
#pragma unroll
            for (int mi = 0; mi < 2; mi++) {
                uint32_t arow = wm * 32 + mi * 16 + (grp & 1) * 8 + (lane & 7);
                uint32_t ab = arow * 80 + kk * 32 + ((grp >> 1) & 1) * 16;
                ldsm4(ah[kk][mi], base + ab);
            }
#pragma unroll
        for (int ni = 0; ni < 8; ni++) {
            uint32_t bh4[4];
            uint32_t bb = lane * 272 + (wn * 64 + ni * 8) * 2;
            ldsm4t(bh4, base + 10240 + bb);
#pragma unroll
            for (int kk = 0; kk < 2; kk++)
#pragma unroll
                for (int mi = 0; mi < 2; mi++)
                    mma16816h(c[mi][ni], ah[kk][mi], bh4 + kk * 2);
        }
        __syncthreads();
    }
}

// ---------------------------------------------------------------------------
// Kernel 1: qkv via fp16 HMMA; epilogue writes Q/K/V fp16 [bh][d][na].
// ---------------------------------------------------------------------------
__global__ __launch_bounds__(256, 2) void qkv_hmma(const float* __restrict__ bias) {
    extern __shared__ __align__(128) uint8_t shm[];
    float c[2][8][4] = {};
    const int b = blockIdx.z;
    gemm_core(c, shm, g_xf + (size_t)b * (256 * 4096), g_wqf);

    const int t = threadIdx.x, lane = t & 31, wid = t >> 5;
    const int wm = wid >> 1, wn = wid & 1;
    const int nBase = blockIdx.x * 128, oBase = blockIdx.y * 128;
    const int ncol0 = nBase + wn * 64 + (lane & 3) * 2;
#pragma unroll
    for (int mi = 0; mi < 2; mi++)
#pragma unroll
        for (int half = 0; half < 2; half++) {
            int o = oBase + wm * 32 + mi * 16 + half * 8 + (lane >> 2);
            int h = o / 96, rem = o % 96, typ = rem >> 5, d = rem & 31;
            float bo = bias[o];
#pragma unroll
            for (int ni = 0; ni < 8; ni++) {
                int n = ncol0 + ni * 8;
                float v0 = c[mi][ni][half * 2 + 0] + bo;
                float v1 = c[mi][ni][half * 2 + 1] + bo;
                int ba = b * 4 + (n >> 10), na = n & 1023;
                size_t idx = (((size_t)(ba * 8 + h) * 32 + d) << 10) + na;
                if (typ == 0) {
                    const float s = 0.17677669529663687f * 1.4426950408889634f;
                    *(uint32_t*)&g_qf[idx] = h2pack(v0 * s, v1 * s);
                } else if (typ == 1) {
                    *(uint32_t*)&g_kf[idx] = h2pack(v0, v1);
                } else {
                    *(uint32_t*)&g_vp[idx] = h2pack(v0, v1);
                }
            }
        }
}

// ---------------------------------------------------------------------------
// Kernel 2: fp16 HMMA flash attention (unchanged from R16).
// ---------------------------------------------------------------------------
#define ABUF 9216
#define AQOFF (2 * ABUF)
#define ASMEM (AQOFF + 32 * 272)

__global__ __launch_bounds__(128, 4) void attn10() {
    extern __shared__ __align__(128) uint8_t shma[];
    const int t = threadIdx.x;
    const int wid = t >> 5, lane = t & 31;
    const int i0 = blockIdx.x * 128, bh = blockIdx.y;
    const uint32_t sb = smem_to_u32(shma);

    const __half* qp = g_qf + (size_t)bh * 32768;
    const __half* kp = g_kf + (size_t)bh * 32768;
    const __half* vp = g_vp + (size_t)bh * 32768;

#pragma unroll
    for (int e = 0; e < 4; e++) {
        int cid = e * 128 + t;
        int row = cid >> 4, col = cid & 15;
        cp16(sb + AQOFF + row * 272 + col * 16, qp + (size_t)row * 1024 + i0 + col * 8);
    }
    asm volatile("cp.async.commit_group;" ::: "memory");

    auto stage = [&](int buf, int jt) {
        const int j0 = jt * 64;
        uint32_t base = sb + buf * ABUF;
#pragma unroll
        for (int e = 0; e < 4; e++) {
            int cid = e * 128 + t;
            if (cid < 256) {
                int row = cid >> 3, col = cid & 7;
                cp16(base + row * 144 + col * 16, kp + (size_t)row * 1024 + j0 + col * 8);
            } else {
                int c2 = cid - 256;
                int row = c2 >> 3, col = c2 & 7;
                cp16(base + 4608 + row * 144 + col * 16, vp + (size_t)row * 1024 + j0 + col * 8);
            }
        }
        asm volatile("cp.async.commit_group;" ::: "memory");
    };

    stage(0, 0);
    asm volatile("cp.async.wait_group 1;" ::: "memory");
    __syncthreads();

    uint32_t aq[2][2][4];
    {
        int r = lane & 7;
        int rowsel = ((lane >> 4) & 1) * 8;
        int colsel = ((lane >> 3) & 1) * 8;
#pragma unroll
        for (int mi = 0; mi < 2; mi++)
#pragma unroll
            for (int kk = 0; kk < 2; kk++) {
                uint32_t addr = sb + AQOFF + (kk * 16 + rowsel + r) * 272
                                + (wid * 32 + mi * 16 + colsel) * 2;
                ldsm4t(aq[mi][kk], addr);
            }
    }

    const uint32_t bones = ((lane >> 2) == 0) ? 0x3C003C00u : 0u;
    uint32_t bone2[2] = {bones, bones};

    float o[2][4][4];
    float os[2][4];
#pragma unroll
    for (int mi = 0; mi < 2; mi++) {
#pragma unroll
        for (int dt = 0; dt < 4; dt++)
#pragma unroll
            for (int j = 0; j < 4; j++) o[mi][dt][j] = 0.f;
#pragma unroll
        for (int j = 0; j < 4; j++) os[mi][j] = 0.f;
    }

    for (int jt = 0; jt < 16; jt++) {
        if (jt < 15) {
            stage((jt + 1) & 1, jt + 1);
            asm volatile("cp.async.wait_group 1;" ::: "memory");
        } else {
            asm volatile("cp.async.wait_group 0;" ::: "memory");
        }
        __syncthreads();
        const uint32_t kb = sb + (jt & 1) * ABUF;

        uint32_t pa[2][4][4];
#pragma unroll
        for (int nt = 0; nt < 8; nt++) {
            uint32_t bf[4];
            ldsm4t(bf, kb + ((lane >> 3) * 8 + (lane & 7)) * 144 + nt * 16);
            int ks = nt >> 1, sl = (nt & 1) * 2;
#pragma unroll
            for (int mi = 0; mi < 2; mi++) {
                float cfr[4] = {0.f, 0.f, 0.f, 0.f};
                mma16816h(cfr, aq[mi][0], bf + 0);
                mma16816h(cfr, aq[mi][1], bf + 2);
                pa[mi][ks][sl]     = ex2h2(h2pack(cfr[0], cfr[1]));
                pa[mi][ks][sl + 1] = ex2h2(h2pack(cfr[2], cfr[3]));
            }
        }

#pragma unroll
        for (int dt = 0; dt < 4; dt++) {
#pragma unroll
            for (int jh = 0; jh < 2; jh++) {
                uint32_t bv[4];
                ldsm4(bv, kb + 4608 + (dt * 8 + (lane & 7)) * 144 + jh * 64 + (lane >> 3) * 16);
                int ks = jh * 2;
#pragma unroll
                for (int mi = 0; mi < 2; mi++) {
                    mma16816h(o[mi][dt], pa[mi][ks], bv + 0);
                    mma16816h(o[mi][dt], pa[mi][ks + 1], bv + 2);
                }
            }
        }
#pragma unroll
        for (int mi = 0; mi < 2; mi++)
#pragma unroll
            for (int ks = 0; ks < 4; ks++)
                mma16816h(os[mi], pa[mi][ks], bone2);
        __syncthreads();
    }

    const int qlead = lane & ~3;
    const int b = bh >> 5, h = bh & 7, a3 = (bh >> 3) & 3;
    float* outb = g_tmp + (((size_t)(b * 256 + h * 32)) << 12) + (a3 << 10) + i0;
#pragma unroll
    for (int mi = 0; mi < 2; mi++) {
        float l0 = __shfl_sync(0xffffffffu, os[mi][0], qlead);
        float l1 = __shfl_sync(0xffffffffu, os[mi][2], qlead);
        const float inv0 = 1.f / l0, inv1 = 1.f / l1;
        const int r0 = wid * 32 + mi * 16 + (lane >> 2), r1 = r0 + 8;
#pragma unroll
        for (int dt = 0; dt < 4; dt++) {
            int d = dt * 8 + (lane & 3) * 2;
            outb[((size_t)d << 12) + r0]       = o[mi][dt][0] * inv0;
            outb[((size_t)(d + 1) << 12) + r0] = o[mi][dt][1] * inv0;
            outb[((size_t)d << 12) + r1]       = o[mi][dt][2] * inv1;
            outb[((size_t)(d + 1) << 12) + r1] = o[mi][dt][3] * inv1;
        }
    }
}

// ---------------------------------------------------------------------------
// Kernel 3: pe — 2 output rows/thread (rows share 6/7 window rows).
// grid 1024, 256 threads; thread => rows (2*(t>>3), +1) x cols (t&7)*8.
// ---------------------------------------------------------------------------
__global__ __launch_bounds__(256) void pe_kernel(const float* __restrict__ wpe,
                                                 const float* __restrict__ bpe) {
    __shared__ float smp[70][72];
    __shared__ float wsm[49];
    const int bc = blockIdx.x, c = bc & 255, b = bc >> 8, t = threadIdx.x;
    const int h = c >> 5, d = c & 31;
    const __half* vbase = g_vp + (((size_t)(b * 4) * 8 + h) * 32 + d) * 1024;
    if (t < 49) wsm[t] = wpe[c * 49 + t];
    for (int e = t; e < 70 * 70; e += 256) {
        int yy = e / 70, xx = e % 70, y = yy - 3, x = xx - 3;
        float v = 0.f;
        if ((unsigned)y < 64u && (unsigned)x < 64u) {
            int n = y * 64 + x;
            v = __half2float(vbase[(size_t)(n >> 10) * 262144 + (n & 1023)]);
        }
        smp[yy][xx] = v;
    }
    __syncthreads();
    const float bb = bpe[c];
    const float* tsrc = g_tmp + (size_t)bc * 4096;
    const int y0 = (t >> 3) * 2, x0 = (t & 7) * 8;
    float acc0[8], acc1[8];
#pragma unroll
    for (int j = 0; j < 8; j++) { acc0[j] = bb; acc1[j] = bb; }
#pragma unroll
    for (int dy = 0; dy < 8; dy++) {
        float win[16];
        *(float4*)&win[0]  = *(const float4*)&smp[y0 + dy][x0 + 0];
        *(float4*)&win[4]  = *(const float4*)&smp[y0 + dy][x0 + 4];
        *(float4*)&win[8]  = *(const float4*)&smp[y0 + dy][x0 + 8];
        *(float4*)&win[12] = *(const float4*)&smp[y0 + dy][x0 + 12];
        // row y0 uses dy 0..6 (weight row dy); row y0+1 uses dy 1..7 (weight row dy-1)
        if (dy < 7) {
#pragma unroll
            for (int dx = 0; dx < 7; dx++) {
                float wv = wsm[dy * 7 + dx];
#pragma unroll
                for (int j = 0; j < 8; j++) acc0[j] += wv * win[j + dx];
            }
        }
        if (dy >= 1) {
#pragma unroll
            for (int dx = 0; dx < 7; dx++) {
                float wv = wsm[(dy - 1) * 7 + dx];
#pragma unroll
                for (int j = 0; j < 8; j++) acc1[j] += wv * win[j + dx];
            }
        }
    }
#pragma unroll
    for (int r = 0; r < 2; r++) {
        float* acc = r ? acc1 : acc0;
        const int y = y0 + r;
        const size_t p = (size_t)bc * 4096 + y * 64 + x0;
        float4 t0 = *(const float4*)&tsrc[y * 64 + x0];
        float4 t1 = *(const float4*)&tsrc[y * 64 + x0 + 4];
        *(uint4*)&g_tf[p] = make_uint4(h2pack(acc[0] + t0.x, acc[1] + t0.y),
                                       h2pack(acc[2] + t0.z, acc[3] + t0.w),
                                       h2pack(acc[4] + t1.x, acc[5] + t1.y),
                                       h2pack(acc[6] + t1.z, acc[7] + t1.w));
    }
}

// ---------------------------------------------------------------------------
// Kernel 4: proj via fp16 HMMA.
// ---------------------------------------------------------------------------
__global__ __launch_bounds__(256, 2) void proj_hmma(const float* __restrict__ bias,
                                                    float* __restrict__ out) {
    extern __shared__ __align__(128) uint8_t shm[];
    float c[2][8][4] = {};
    const int b = blockIdx.z;
    gemm_core(c, shm, g_tf + (size_t)b * (256 * 4096), g_wpf);

    const int t = threadIdx.x, lane = t & 31, wid = t >> 5;
    const int wm = wid >> 1, wn = wid & 1;
    const int nBase = blockIdx.x * 128, oBase = blockIdx.y * 128;
    const int ncol0 = nBase + wn * 64 + (lane & 3) * 2;
#pragma unroll
    for (int mi = 0; mi < 2; mi++)
#pragma unroll
        for (int half = 0; half < 2; half++) {
            int o = oBase + wm * 32 + mi * 16 + half * 8 + (lane >> 2);
            float bo = bias[o];
            float* orow = out + (((size_t)(b * 256 + o)) << 12);
#pragma unroll
            for (int ni = 0; ni < 8; ni++) {
                int n = ncol0 + ni * 8;
                *(float2*)&orow[n] = make_float2(c[mi][ni][half * 2 + 0] + bo,
                                                 c[mi][ni][half * 2 + 1] + bo);
            }
        }
}

// ---------------------------------------------------------------------------
extern "C" void kernel_launch(void* const* d_in, const int* in_sizes, int n_in,
                              void* d_out, int out_size) {
    const float* x      = (const float*)d_in[0];
    const float* w_qkv  = (const float*)d_in[1];
    const float* b_qkv  = (const float*)d_in[2];
    const float* w_pe   = (const float*)d_in[3];
    const float* b_pe   = (const float*)d_in[4];
    const float* w_proj = (const float*)d_in[5];
    const float* b_proj = (const float*)d_in[6];
    float* out = (float*)d_out;

    cudaFuncSetAttribute(qkv_hmma, cudaFuncAttributeMaxDynamicSharedMemorySize, GSMEM);
    cudaFuncSetAttribute(proj_hmma, cudaFuncAttributeMaxDynamicSharedMemorySize, GSMEM);
    cudaFuncSetAttribute(attn10, cudaFuncAttributeMaxDynamicSharedMemorySize, ASMEM);

    conv_all<<<4352, 256>>>(x, w_qkv, w_proj);
    qkv_hmma<<<dim3(32, 6, 4), 256, GSMEM>>>(b_qkv);
    attn10<<<dim3(8, 128), 128, ASMEM>>>();
    pe_kernel<<<1024, 256>>>(w_pe, b_pe);
    proj_hmma<<<dim3(32, 2, 4), 256, GSMEM>>>(b_proj, out);
}